// round 11
// baseline (speedup 1.0000x reference)
#include <cuda_runtime.h>

#define BATCH 32
#define HH 256
#define WW 256
#define CC 16
#define KK 32
#define NSTEPS 5
#define NPIX (BATCH*HH*WW)           // 2097152
#define NELEM (NPIX*CC)
#define NT2 (NPIX/512)               // 4096 tiles of 16x32

typedef unsigned long long ull;

// ---------------- static device scratch ----------------
__device__ float g_M[9*CC*KK];       // [tap][c][k]
__device__ float g_P[CC*KK];         // beta*cb
__device__ float g_Q[CC*KK];         // 1-beta
__device__ float g_csq[KK];
__device__ float g_sigD[KK];
__device__ float g_sse[NSTEPS];
__device__ unsigned g_used[NSTEPS];
__device__ unsigned char g_idxA[NPIX];
__device__ unsigned char g_idxB[NPIX];

// ---------------- f32x2 helpers ----------------
__device__ __forceinline__ ull pack2f(float lo, float hi) {
    ull d;
    asm("mov.b64 %0,{%1,%2};" : "=l"(d) : "r"(__float_as_uint(lo)), "r"(__float_as_uint(hi)));
    return d;
}
__device__ __forceinline__ void unpack2f(ull v, float& lo, float& hi) {
    unsigned a, b;
    asm("mov.b64 {%0,%1},%2;" : "=r"(a), "=r"(b) : "l"(v));
    lo = __uint_as_float(a); hi = __uint_as_float(b);
}
__device__ __forceinline__ ull fma2(ull a, ull b, ull c) {
    ull d;
    asm("fma.rn.f32x2 %0,%1,%2,%3;" : "=l"(d) : "l"(a), "l"(b), "l"(c));
    return d;
}
__device__ __forceinline__ ull add2(ull a, ull b) {
    ull d;
    asm("add.rn.f32x2 %0,%1,%2;" : "=l"(d) : "l"(a), "l"(b));
    return d;
}

// ---------------- table precompute ----------------
__global__ void k_tables(const float* __restrict__ up1_w,
                         const float* __restrict__ tau_w, const float* __restrict__ tau_b,
                         const float* __restrict__ cb,
                         const float* __restrict__ dec_w, const float* __restrict__ dec_b) {
    int tid = threadIdx.x;
    for (int e = tid; e < 9*CC*KK; e += blockDim.x) {
        int k = e & 31; int c = (e >> 5) & 15; int tap = e >> 9;
        float acc = 0.f;
        #pragma unroll
        for (int ci = 0; ci < CC; ci++)
            acc = fmaf(up1_w[(c*CC+ci)*9 + tap], cb[k*CC+ci], acc);
        g_M[e] = acc;
    }
    for (int e = tid; e < CC*KK; e += blockDim.x) {
        int k = e & 31; int c = e >> 5;
        float t = tau_b[c];
        #pragma unroll
        for (int ci = 0; ci < CC; ci++)
            t = fmaf(tau_w[c*CC+ci], cb[k*CC+ci], t);
        float beta = 1.f / (1.f + expf(-t));
        g_P[e] = beta * cb[k*CC+c];
        g_Q[e] = 1.f - beta;
    }
    for (int k = tid; k < KK; k += blockDim.x) {
        float s = 0.f, d = dec_b[0];
        #pragma unroll
        for (int c = 0; c < CC; c++) { float v = cb[k*CC+c]; s = fmaf(v, v, s); d = fmaf(dec_w[c], v, d); }
        g_csq[k] = s;
        g_sigD[k] = 1.f / (1.f + expf(-d));
    }
    if (tid < NSTEPS) { g_sse[tid] = 0.f; g_used[tid] = 0u; }
}

// ---------------- block reduce + atomic ----------------
__device__ __forceinline__ void block_accumulate(float loss, unsigned mask, int slot,
                                                 float* red, unsigned* redu) {
    #pragma unroll
    for (int o = 16; o; o >>= 1) loss += __shfl_xor_sync(0xffffffffu, loss, o);
    mask = __reduce_or_sync(0xffffffffu, mask);
    int lane = threadIdx.x & 31, wid = threadIdx.x >> 5;
    if (lane == 0) { red[wid] = loss; redu[wid] = mask; }
    __syncthreads();
    if (threadIdx.x == 0) {
        float s = 0.f; unsigned m = 0u;
        int nw = blockDim.x >> 5;
        for (int i = 0; i < nw; i++) { s += red[i]; m |= redu[i]; }
        atomicAdd(&g_sse[slot], s);
        atomicOr(&g_used[slot], m);
    }
}

// ---------------- dual-pixel VQ, codebook processed in 2 halves ----------------
__device__ __forceinline__ void vq2_seq(const float* zA, const float* zB,
                                        float zsqa, float zsqb,
                                        const ull* s_cb2n, const ull* s_csq2,
                                        int& bka, int& bkb, float& la, float& lb) {
    float besta = 3.4e38f, bestb = 3.4e38f; bka = 0; bkb = 0;
    #pragma unroll
    for (int h = 0; h < 2; h++) {
        ull da[8], db[8];
        #pragma unroll
        for (int j = 0; j < 8; j++) { ull c0 = s_csq2[h*8 + j]; da[j] = c0; db[j] = c0; }
        #pragma unroll
        for (int c = 0; c < CC; c++) {
            ull za = pack2f(zA[c], zA[c]);
            ull zb = pack2f(zB[c], zB[c]);
            const ulonglong2* cp = (const ulonglong2*)&s_cb2n[c*16 + h*8];
            #pragma unroll
            for (int jj = 0; jj < 4; jj++) {
                ulonglong2 w = cp[jj];
                da[2*jj]   = fma2(za, w.x, da[2*jj]);
                da[2*jj+1] = fma2(za, w.y, da[2*jj+1]);
                db[2*jj]   = fma2(zb, w.x, db[2*jj]);
                db[2*jj+1] = fma2(zb, w.y, db[2*jj+1]);
            }
        }
        #pragma unroll
        for (int j = 0; j < 8; j++) {
            float lo, hi;
            unpack2f(da[j], lo, hi);
            if (lo < besta) { besta = lo; bka = h*16 + 2*j; }
            if (hi < besta) { besta = hi; bka = h*16 + 2*j + 1; }
            unpack2f(db[j], lo, hi);
            if (lo < bestb) { bestb = lo; bkb = h*16 + 2*j; }
            if (hi < bestb) { bestb = hi; bkb = h*16 + 2*j + 1; }
        }
    }
    la = zsqa + besta;
    lb = zsqb + bestb;
}

// ---------------- fused stem + step 1: 16x32 tile, 256 threads, 2 px/thread ----------------
__global__ __launch_bounds__(256, 3)
void k_step1(const float* __restrict__ x,
             const float* __restrict__ stem_w, const float* __restrict__ stem_b,
             const float* __restrict__ up1_w, const float* __restrict__ up1_b,
             const float* __restrict__ up2_w, const float* __restrict__ up2_b,
             const float* __restrict__ tau_w, const float* __restrict__ tau_b,
             const float* __restrict__ cb) {
    __shared__ float xs[36*20];
    __shared__ float s0[CC][34*18];
    __shared__ float s_sw[CC*9];
    __shared__ float s_sb[CC];
    __shared__ __align__(16) ull s_w2[CC*9*8];
    __shared__ __align__(16) ull s_tw2[CC*8];
    __shared__ __align__(16) ull s_u2w2[CC*8];
    __shared__ __align__(16) ull s_cb2n[CC*16];
    __shared__ __align__(16) ull s_csq2[16];
    __shared__ __align__(16) ull s_bu1[8];
    __shared__ __align__(16) ull s_bu2[8];
    __shared__ __align__(16) ull s_bt[8];
    __shared__ float red[8]; __shared__ unsigned redu[8];

    int tid = threadIdx.x;
    int tx = tid & 15, ty = tid >> 4;      // ty 0..15, rows 2ty, 2ty+1 of 32-row tile
    int gx0 = blockIdx.x * 16, gy0 = blockIdx.y * 32, b = blockIdx.z;
    const float* xb = x + b * HH * WW;

    for (int e = tid; e < CC*9*8; e += 256) {
        int q = e & 7; int t = (e >> 3) % 9; int ci = e / 72;
        s_w2[e] = pack2f(up1_w[(2*q*CC + ci)*9 + t], up1_w[((2*q+1)*CC + ci)*9 + t]);
    }
    for (int e = tid; e < CC*8; e += 256) {
        int q = e & 7; int ci = e >> 3;
        s_tw2[e]  = pack2f(tau_w[2*q*CC + ci],  tau_w[(2*q+1)*CC + ci]);
        s_u2w2[e] = pack2f(up2_w[2*q*CC + ci],  up2_w[(2*q+1)*CC + ci]);
    }
    for (int e = tid; e < CC*16; e += 256) {
        int j = e & 15; int c = e >> 4;
        s_cb2n[e] = pack2f(-2.f*cb[2*j*CC + c], -2.f*cb[(2*j+1)*CC + c]);
    }
    if (tid < CC*9) s_sw[tid] = stem_w[tid];
    if (tid < CC) s_sb[tid] = stem_b[tid];
    if (tid < 16) s_csq2[tid] = pack2f(g_csq[2*tid], g_csq[2*tid+1]);
    if (tid < 8) {
        s_bu1[tid] = pack2f(up1_b[2*tid], up1_b[2*tid+1]);
        s_bu2[tid] = pack2f(up2_b[2*tid], up2_b[2*tid+1]);
        s_bt[tid]  = pack2f(tau_b[2*tid], tau_b[2*tid+1]);
    }
    for (int p = tid; p < 36*20; p += 256) {
        int iy = p / 20, ix = p % 20;
        int gy = gy0 - 2 + iy, gx = gx0 - 2 + ix;
        xs[p] = (gy >= 0 && gy < HH && gx >= 0 && gx < WW) ? xb[gy*WW + gx] : 0.f;
    }
    __syncthreads();

    // ---- stem over 34x18 halo: per-thread pixel descriptors, weights in regs ----
    {
        int   xoff[3]; bool pval[3];
        #pragma unroll
        for (int i = 0; i < 3; i++) {
            int p = tid + i*256;
            if (p < 34*18) {
                int ly = p / 18, lx = p % 18;
                int gy = gy0 - 1 + ly, gx = gx0 - 1 + lx;
                pval[i] = (gy >= 0 && gy < HH && gx >= 0 && gx < WW);
                xoff[i] = ly*20 + lx;
            } else { pval[i] = false; xoff[i] = 0; }
        }
        for (int c = 0; c < CC; c++) {
            float w[9];
            #pragma unroll
            for (int t = 0; t < 9; t++) w[t] = s_sw[c*9 + t];
            float bb = s_sb[c];
            #pragma unroll
            for (int i = 0; i < 3; i++) {
                int p = tid + i*256;
                if (p < 34*18) {
                    float acc = 0.f;
                    if (pval[i]) {
                        acc = bb;
                        #pragma unroll
                        for (int t = 0; t < 9; t++)
                            acc = fmaf(w[t], xs[xoff[i] + (t/3)*20 + t%3], acc);
                        acc = fmaxf(acc, 0.f);
                    }
                    s0[c][p] = acc;
                }
            }
        }
    }
    __syncthreads();

    // ---- conv3x3 16->16, 2 px/thread ----
    ull y2a[8], y2b[8];
    #pragma unroll
    for (int q = 0; q < 8; q++) { y2a[q] = s_bu1[q]; y2b[q] = s_bu1[q]; }
    #pragma unroll 4
    for (int ci = 0; ci < CC; ci++) {
        const float* s0p = &s0[ci][0];
        #pragma unroll
        for (int tc = 0; tc < 3; tc++) {
            float v0 = s0p[(2*ty+0)*18 + tx + tc];
            float v1 = s0p[(2*ty+1)*18 + tx + tc];
            float v2 = s0p[(2*ty+2)*18 + tx + tc];
            float v3 = s0p[(2*ty+3)*18 + tx + tc];
            #pragma unroll
            for (int tr = 0; tr < 3; tr++) {
                int t = tr*3 + tc;
                float va = (tr == 0) ? v0 : ((tr == 1) ? v1 : v2);
                float vb = (tr == 0) ? v1 : ((tr == 1) ? v2 : v3);
                ull vva = pack2f(va, va), vvb = pack2f(vb, vb);
                const ulonglong2* wp = (const ulonglong2*)&s_w2[(ci*9 + t)*8];
                #pragma unroll
                for (int qq = 0; qq < 4; qq++) {
                    ulonglong2 w = wp[qq];
                    y2a[2*qq]   = fma2(vva, w.x, y2a[2*qq]);
                    y2a[2*qq+1] = fma2(vva, w.y, y2a[2*qq+1]);
                    y2b[2*qq]   = fma2(vvb, w.x, y2b[2*qq]);
                    y2b[2*qq+1] = fma2(vvb, w.y, y2b[2*qq+1]);
                }
            }
        }
    }

    // ---- delta = up2 @ relu(y) ----
    ull d2a[8], d2b[8];
    #pragma unroll
    for (int q = 0; q < 8; q++) { d2a[q] = s_bu2[q]; d2b[q] = s_bu2[q]; }
    #pragma unroll
    for (int q = 0; q < 8; q++) {
        float a0, a1, b0, b1;
        unpack2f(y2a[q], a0, a1); unpack2f(y2b[q], b0, b1);
        a0 = fmaxf(a0, 0.f); a1 = fmaxf(a1, 0.f);
        b0 = fmaxf(b0, 0.f); b1 = fmaxf(b1, 0.f);
        #pragma unroll
        for (int s = 0; s < 2; s++) {
            int ci = 2*q + s;
            float fa = s ? a1 : a0, fb = s ? b1 : b0;
            ull va = pack2f(fa, fa), vb = pack2f(fb, fb);
            const ulonglong2* wp = (const ulonglong2*)&s_u2w2[ci*8];
            #pragma unroll
            for (int qq = 0; qq < 4; qq++) {
                ulonglong2 w = wp[qq];
                d2a[2*qq]   = fma2(va, w.x, d2a[2*qq]);
                d2a[2*qq+1] = fma2(va, w.y, d2a[2*qq+1]);
                d2b[2*qq]   = fma2(vb, w.x, d2b[2*qq]);
                d2b[2*qq+1] = fma2(vb, w.y, d2b[2*qq+1]);
            }
        }
    }

    // ---- tau (center values read from smem) ----
    int ctra = (2*ty+1)*18 + (tx+1);
    int ctrb = (2*ty+2)*18 + (tx+1);
    ull t2a[8], t2b[8];
    #pragma unroll
    for (int q = 0; q < 8; q++) { t2a[q] = s_bt[q]; t2b[q] = s_bt[q]; }
    #pragma unroll 4
    for (int ci = 0; ci < CC; ci++) {
        float fa = s0[ci][ctra], fb = s0[ci][ctrb];
        ull va = pack2f(fa, fa), vb = pack2f(fb, fb);
        const ulonglong2* wp = (const ulonglong2*)&s_tw2[ci*8];
        #pragma unroll
        for (int qq = 0; qq < 4; qq++) {
            ulonglong2 w = wp[qq];
            t2a[2*qq]   = fma2(va, w.x, t2a[2*qq]);
            t2a[2*qq+1] = fma2(va, w.y, t2a[2*qq+1]);
            t2b[2*qq]   = fma2(vb, w.x, t2b[2*qq]);
            t2b[2*qq+1] = fma2(vb, w.y, t2b[2*qq+1]);
        }
    }

    // ---- blend + zsq ----
    float zA[CC], zB[CC]; float zsqa = 0.f, zsqb = 0.f;
    #pragma unroll
    for (int q = 0; q < 8; q++) {
        float tlo, thi, dlo, dhi;
        unpack2f(t2a[q], tlo, thi); unpack2f(d2a[q], dlo, dhi);
        {
            float blo = 1.f / (1.f + __expf(-tlo));
            float bhi = 1.f / (1.f + __expf(-thi));
            float zlo = fmaf(blo, s0[2*q][ctra],   (1.f - blo) * dlo);
            float zhi = fmaf(bhi, s0[2*q+1][ctra], (1.f - bhi) * dhi);
            zsqa = fmaf(zlo, zlo, zsqa); zsqa = fmaf(zhi, zhi, zsqa);
            zA[2*q] = zlo; zA[2*q+1] = zhi;
        }
        unpack2f(t2b[q], tlo, thi); unpack2f(d2b[q], dlo, dhi);
        {
            float blo = 1.f / (1.f + __expf(-tlo));
            float bhi = 1.f / (1.f + __expf(-thi));
            float zlo = fmaf(blo, s0[2*q][ctrb],   (1.f - blo) * dlo);
            float zhi = fmaf(bhi, s0[2*q+1][ctrb], (1.f - bhi) * dhi);
            zsqb = fmaf(zlo, zlo, zsqb); zsqb = fmaf(zhi, zhi, zsqb);
            zB[2*q] = zlo; zB[2*q+1] = zhi;
        }
    }

    int bka, bkb; float la, lb;
    vq2_seq(zA, zB, zsqa, zsqb, s_cb2n, s_csq2, bka, bkb, la, lb);

    int gya = gy0 + 2*ty;
    g_idxA[(b*HH + gya    )*WW + gx0 + tx] = (unsigned char)bka;
    g_idxA[(b*HH + gya + 1)*WW + gx0 + tx] = (unsigned char)bkb;
    block_accumulate(la + lb, (1u << bka) | (1u << bkb), 0, red, redu);
}

// ---------------- steps 2..5 common body (round-4 layout), templated on LAST ----------------
template<int LAST>
__device__ __forceinline__ void step_body(const float* up1_b, const float* up2_w,
                                          const float* up2_b, const float* cb,
                                          float* out, int slot) {
    __shared__ __align__(16) ull s_M2[9*8*33];    // [t][q][k], sentinel k=32 -> 0
    __shared__ __align__(16) ull s_P2[8*32];
    __shared__ __align__(16) ull s_Q2[8*32];
    __shared__ __align__(16) ull s_cb2n[CC*16];
    __shared__ __align__(16) ull s_csq2[16];
    __shared__ __align__(16) ull s_bu1[8];
    __shared__ __align__(16) ull s_bu2[8];
    __shared__ __align__(16) ull s_u2w2[CC*8];
    __shared__ unsigned char s_idx[34*18];
    __shared__ float s_sigD[KK];
    __shared__ float red[8]; __shared__ unsigned redu[8];

    int tid = threadIdx.x;
    for (int e = tid; e < 9*8*33; e += 256) {
        int k = e % 33; int q = (e/33) & 7; int t = e/(33*8);
        float lo = 0.f, hi = 0.f;
        if (k < 32) { lo = g_M[(t*CC + 2*q)*KK + k]; hi = g_M[(t*CC + 2*q+1)*KK + k]; }
        s_M2[e] = pack2f(lo, hi);
    }
    for (int e = tid; e < 8*32; e += 256) {
        int k = e & 31; int q = e >> 5;
        s_P2[e] = pack2f(g_P[2*q*KK + k], g_P[(2*q+1)*KK + k]);
        s_Q2[e] = pack2f(g_Q[2*q*KK + k], g_Q[(2*q+1)*KK + k]);
    }
    for (int e = tid; e < CC*16; e += 256) {
        int j = e & 15; int c = e >> 4;
        s_cb2n[e] = pack2f(-2.f*cb[2*j*CC + c], -2.f*cb[(2*j+1)*CC + c]);
    }
    if (tid < 16) s_csq2[tid] = pack2f(g_csq[2*tid], g_csq[2*tid+1]);
    if (tid < 8) {
        s_bu1[tid] = pack2f(up1_b[2*tid], up1_b[2*tid+1]);
        s_bu2[tid] = pack2f(up2_b[2*tid], up2_b[2*tid+1]);
    }
    for (int e = tid; e < CC*8; e += 256) {
        int q = e & 7; int ci = e >> 3;
        s_u2w2[e] = pack2f(up2_w[2*q*CC + ci], up2_w[(2*q+1)*CC + ci]);
    }
    if (LAST) { if (tid < KK) s_sigD[tid] = g_sigD[tid]; }

    const unsigned char* ibuf = (slot & 1) ? g_idxA : g_idxB;
    unsigned char* obuf       = (slot & 1) ? g_idxB : g_idxA;

    int tx = tid & 15, ty = tid >> 4;
    float loc_loss = 0.f; unsigned loc_mask = 0u;

    for (int tile = blockIdx.x; tile < NT2; tile += gridDim.x) {
        int b = tile >> 7; int rem = tile & 127;
        int gy0 = (rem >> 4) << 5, gx0 = (rem & 15) << 4;
        const unsigned char* ib = ibuf + b * HH * WW;

        __syncthreads();
        for (int p = tid; p < 34*18; p += 256) {
            int iy = p / 18, ix = p % 18;
            int gy = gy0 - 1 + iy, gx = gx0 - 1 + ix;
            s_idx[p] = (gy >= 0 && gy < HH && gx >= 0 && gx < WW) ? ib[gy*WW + gx] : 32;
        }
        __syncthreads();

        // conv via table adds; idx rows shared between the 2 pixels
        ull y2a[8], y2b[8];
        #pragma unroll
        for (int q = 0; q < 8; q++) { y2a[q] = s_bu1[q]; y2b[q] = s_bu1[q]; }
        #pragma unroll
        for (int tc = 0; tc < 3; tc++) {
            int i0 = s_idx[(2*ty+0)*18 + tx + tc];
            int i1 = s_idx[(2*ty+1)*18 + tx + tc];
            int i2 = s_idx[(2*ty+2)*18 + tx + tc];
            int i3 = s_idx[(2*ty+3)*18 + tx + tc];
            #pragma unroll
            for (int tr = 0; tr < 3; tr++) {
                int t = tr*3 + tc;
                int ka = (tr == 0) ? i0 : ((tr == 1) ? i1 : i2);
                int kb = (tr == 0) ? i1 : ((tr == 1) ? i2 : i3);
                const ull* Ma = &s_M2[t*8*33 + ka];
                const ull* Mb = &s_M2[t*8*33 + kb];
                #pragma unroll
                for (int q = 0; q < 8; q++) {
                    y2a[q] = add2(y2a[q], Ma[q*33]);
                    y2b[q] = add2(y2b[q], Mb[q*33]);
                }
            }
        }

        // delta, relu+unpack on the fly
        ull d2a[8], d2b[8];
        #pragma unroll
        for (int q = 0; q < 8; q++) { d2a[q] = s_bu2[q]; d2b[q] = s_bu2[q]; }
        #pragma unroll
        for (int q = 0; q < 8; q++) {
            float a0, a1, b0, b1;
            unpack2f(y2a[q], a0, a1); unpack2f(y2b[q], b0, b1);
            a0 = fmaxf(a0, 0.f); a1 = fmaxf(a1, 0.f);
            b0 = fmaxf(b0, 0.f); b1 = fmaxf(b1, 0.f);
            #pragma unroll
            for (int s = 0; s < 2; s++) {
                int ci = 2*q + s;
                float fa = s ? a1 : a0, fb = s ? b1 : b0;
                ull va = pack2f(fa, fa), vb = pack2f(fb, fb);
                const ulonglong2* wp = (const ulonglong2*)&s_u2w2[ci*8];
                #pragma unroll
                for (int qq = 0; qq < 4; qq++) {
                    ulonglong2 w = wp[qq];
                    d2a[2*qq]   = fma2(va, w.x, d2a[2*qq]);
                    d2a[2*qq+1] = fma2(va, w.y, d2a[2*qq+1]);
                    d2b[2*qq]   = fma2(vb, w.x, d2b[2*qq]);
                    d2b[2*qq+1] = fma2(vb, w.y, d2b[2*qq+1]);
                }
            }
        }

        // blend via P/Q tables on center codes
        int kca = s_idx[(2*ty+1)*18 + tx + 1];
        int kcb = s_idx[(2*ty+2)*18 + tx + 1];
        float zA[CC], zB[CC]; float zsqa = 0.f, zsqb = 0.f;
        #pragma unroll
        for (int q = 0; q < 8; q++) {
            ull za = fma2(s_Q2[q*32 + kca], d2a[q], s_P2[q*32 + kca]);
            ull zb = fma2(s_Q2[q*32 + kcb], d2b[q], s_P2[q*32 + kcb]);
            float lo, hi;
            unpack2f(za, lo, hi); zsqa = fmaf(lo, lo, zsqa); zsqa = fmaf(hi, hi, zsqa);
            zA[2*q] = lo; zA[2*q+1] = hi;
            unpack2f(zb, lo, hi); zsqb = fmaf(lo, lo, zsqb); zsqb = fmaf(hi, hi, zsqb);
            zB[2*q] = lo; zB[2*q+1] = hi;
        }

        int bka, bkb; float la, lb;
        vq2_seq(zA, zB, zsqa, zsqb, s_cb2n, s_csq2, bka, bkb, la, lb);

        int gya = gy0 + 2*ty;
        if (LAST) {
            out[(b*HH + gya    )*WW + gx0 + tx] = s_sigD[bka];
            out[(b*HH + gya + 1)*WW + gx0 + tx] = s_sigD[bkb];
        } else {
            obuf[(b*HH + gya    )*WW + gx0 + tx] = (unsigned char)bka;
            obuf[(b*HH + gya + 1)*WW + gx0 + tx] = (unsigned char)bkb;
        }
        loc_loss += la + lb;
        loc_mask |= (1u << bka) | (1u << bkb);
    }
    __syncthreads();
    block_accumulate(loc_loss, loc_mask, slot, red, redu);
}

__global__ __launch_bounds__(256, 4)
void k_step_mid(const float* __restrict__ up1_b, const float* __restrict__ up2_w,
                const float* __restrict__ up2_b, const float* __restrict__ cb, int slot) {
    step_body<0>(up1_b, up2_w, up2_b, cb, nullptr, slot);
}

__global__ __launch_bounds__(256, 4)
void k_step_last(const float* __restrict__ up1_b, const float* __restrict__ up2_w,
                 const float* __restrict__ up2_b, const float* __restrict__ cb,
                 float* __restrict__ out) {
    step_body<1>(up1_b, up2_w, up2_b, cb, out, 4);
}

// ---------------- scalars ----------------
__global__ void k_final(float* __restrict__ out) {
    float vq = 0.f, us = 0.f;
    #pragma unroll
    for (int s = 0; s < NSTEPS; s++) {
        vq += 1.25f * g_sse[s] / (float)NELEM;
        us += (float)__popc(g_used[s]) / (float)KK;
    }
    out[NPIX]     = vq / (float)NSTEPS;
    out[NPIX + 1] = us / (float)NSTEPS;
}

extern "C" void kernel_launch(void* const* d_in, const int* in_sizes, int n_in,
                              void* d_out, int out_size) {
    const float* x      = (const float*)d_in[0];
    const float* stem_w = (const float*)d_in[1];
    const float* stem_b = (const float*)d_in[2];
    const float* up1_w  = (const float*)d_in[3];
    const float* up1_b  = (const float*)d_in[4];
    const float* up2_w  = (const float*)d_in[5];
    const float* up2_b  = (const float*)d_in[6];
    const float* tau_w  = (const float*)d_in[7];
    const float* tau_b  = (const float*)d_in[8];
    const float* cb     = (const float*)d_in[9];
    const float* dec_w  = (const float*)d_in[10];
    const float* dec_b  = (const float*)d_in[11];
    float* out = (float*)d_out;

    k_tables<<<1, 512>>>(up1_w, tau_w, tau_b, cb, dec_w, dec_b);

    dim3 grid1(WW/16, HH/32, BATCH);
    k_step1<<<grid1, 256>>>(x, stem_w, stem_b, up1_w, up1_b, up2_w, up2_b, tau_w, tau_b, cb);
    for (int s = 1; s < 4; s++)
        k_step_mid<<<1332, 256>>>(up1_b, up2_w, up2_b, cb, s);
    k_step_last<<<1332, 256>>>(up1_b, up2_w, up2_b, cb, out);

    k_final<<<1, 1>>>(out);
}

// round 12
// speedup vs baseline: 1.1222x; 1.1222x over previous
#include <cuda_runtime.h>

#define BATCH 32
#define HH 256
#define WW 256
#define CC 16
#define KK 32
#define NSTEPS 5
#define NPIX (BATCH*HH*WW)           // 2097152
#define NELEM (NPIX*CC)
#define NT2 (NPIX/512)               // 4096 tiles of 16x32

typedef unsigned long long ull;

// ---------------- static device scratch ----------------
__device__ float g_M[9*CC*KK];       // [tap][c][k]
__device__ float g_P[CC*KK];         // beta*cb
__device__ float g_Q[CC*KK];         // 1-beta
__device__ float g_csq[KK];
__device__ float g_sigD[KK];
__device__ float g_sse[NSTEPS];
__device__ unsigned g_used[NSTEPS];
__device__ unsigned char g_idxA[NPIX];
__device__ unsigned char g_idxB[NPIX];

// ---------------- f32x2 helpers ----------------
__device__ __forceinline__ ull pack2f(float lo, float hi) {
    ull d;
    asm("mov.b64 %0,{%1,%2};" : "=l"(d) : "r"(__float_as_uint(lo)), "r"(__float_as_uint(hi)));
    return d;
}
__device__ __forceinline__ void unpack2f(ull v, float& lo, float& hi) {
    unsigned a, b;
    asm("mov.b64 {%0,%1},%2;" : "=r"(a), "=r"(b) : "l"(v));
    lo = __uint_as_float(a); hi = __uint_as_float(b);
}
__device__ __forceinline__ ull fma2(ull a, ull b, ull c) {
    ull d;
    asm("fma.rn.f32x2 %0,%1,%2,%3;" : "=l"(d) : "l"(a), "l"(b), "l"(c));
    return d;
}
__device__ __forceinline__ ull add2(ull a, ull b) {
    ull d;
    asm("add.rn.f32x2 %0,%1,%2;" : "=l"(d) : "l"(a), "l"(b));
    return d;
}

// ---------------- table precompute ----------------
__global__ void k_tables(const float* __restrict__ up1_w,
                         const float* __restrict__ tau_w, const float* __restrict__ tau_b,
                         const float* __restrict__ cb,
                         const float* __restrict__ dec_w, const float* __restrict__ dec_b) {
    int tid = threadIdx.x;
    for (int e = tid; e < 9*CC*KK; e += blockDim.x) {
        int k = e & 31; int c = (e >> 5) & 15; int tap = e >> 9;
        float acc = 0.f;
        #pragma unroll
        for (int ci = 0; ci < CC; ci++)
            acc = fmaf(up1_w[(c*CC+ci)*9 + tap], cb[k*CC+ci], acc);
        g_M[e] = acc;
    }
    for (int e = tid; e < CC*KK; e += blockDim.x) {
        int k = e & 31; int c = e >> 5;
        float t = tau_b[c];
        #pragma unroll
        for (int ci = 0; ci < CC; ci++)
            t = fmaf(tau_w[c*CC+ci], cb[k*CC+ci], t);
        float beta = 1.f / (1.f + expf(-t));
        g_P[e] = beta * cb[k*CC+c];
        g_Q[e] = 1.f - beta;
    }
    for (int k = tid; k < KK; k += blockDim.x) {
        float s = 0.f, d = dec_b[0];
        #pragma unroll
        for (int c = 0; c < CC; c++) { float v = cb[k*CC+c]; s = fmaf(v, v, s); d = fmaf(dec_w[c], v, d); }
        g_csq[k] = s;
        g_sigD[k] = 1.f / (1.f + expf(-d));
    }
    if (tid < NSTEPS) { g_sse[tid] = 0.f; g_used[tid] = 0u; }
}

// ---------------- block reduce + atomic ----------------
__device__ __forceinline__ void block_accumulate(float loss, unsigned mask, int slot,
                                                 float* red, unsigned* redu) {
    #pragma unroll
    for (int o = 16; o; o >>= 1) loss += __shfl_xor_sync(0xffffffffu, loss, o);
    mask = __reduce_or_sync(0xffffffffu, mask);
    int lane = threadIdx.x & 31, wid = threadIdx.x >> 5;
    if (lane == 0) { red[wid] = loss; redu[wid] = mask; }
    __syncthreads();
    if (threadIdx.x == 0) {
        float s = 0.f; unsigned m = 0u;
        int nw = blockDim.x >> 5;
        for (int i = 0; i < nw; i++) { s += red[i]; m |= redu[i]; }
        atomicAdd(&g_sse[slot], s);
        atomicOr(&g_used[slot], m);
    }
}

// ---------------- dual-pixel VQ, codebook processed in 2 halves ----------------
__device__ __forceinline__ void vq2_seq(const float* zA, const float* zB,
                                        float zsqa, float zsqb,
                                        const ull* s_cb2n, const ull* s_csq2,
                                        int& bka, int& bkb, float& la, float& lb) {
    float besta = 3.4e38f, bestb = 3.4e38f; bka = 0; bkb = 0;
    #pragma unroll
    for (int h = 0; h < 2; h++) {
        ull da[8], db[8];
        #pragma unroll
        for (int j = 0; j < 8; j++) { ull c0 = s_csq2[h*8 + j]; da[j] = c0; db[j] = c0; }
        #pragma unroll
        for (int c = 0; c < CC; c++) {
            ull za = pack2f(zA[c], zA[c]);
            ull zb = pack2f(zB[c], zB[c]);
            const ulonglong2* cp = (const ulonglong2*)&s_cb2n[c*16 + h*8];
            #pragma unroll
            for (int jj = 0; jj < 4; jj++) {
                ulonglong2 w = cp[jj];
                da[2*jj]   = fma2(za, w.x, da[2*jj]);
                da[2*jj+1] = fma2(za, w.y, da[2*jj+1]);
                db[2*jj]   = fma2(zb, w.x, db[2*jj]);
                db[2*jj+1] = fma2(zb, w.y, db[2*jj+1]);
            }
        }
        #pragma unroll
        for (int j = 0; j < 8; j++) {
            float lo, hi;
            unpack2f(da[j], lo, hi);
            if (lo < besta) { besta = lo; bka = h*16 + 2*j; }
            if (hi < besta) { besta = hi; bka = h*16 + 2*j + 1; }
            unpack2f(db[j], lo, hi);
            if (lo < bestb) { bestb = lo; bkb = h*16 + 2*j; }
            if (hi < bestb) { bestb = hi; bkb = h*16 + 2*j + 1; }
        }
    }
    la = zsqa + besta;
    lb = zsqb + bestb;
}

// ---------------- fused stem + step 1: 16x16 tile, 128 threads, 2 px/thread ----------------
__global__ __launch_bounds__(128, 6)
void k_step1(const float* __restrict__ x,
             const float* __restrict__ stem_w, const float* __restrict__ stem_b,
             const float* __restrict__ up1_w, const float* __restrict__ up1_b,
             const float* __restrict__ up2_w, const float* __restrict__ up2_b,
             const float* __restrict__ tau_w, const float* __restrict__ tau_b,
             const float* __restrict__ cb) {
    __shared__ float xs[20*20];
    __shared__ float s0[CC][18*18];
    __shared__ float s_sw[CC*9];
    __shared__ float s_sb[CC];
    __shared__ __align__(16) ull s_w2[CC*9*8];
    __shared__ __align__(16) ull s_tw2[CC*8];
    __shared__ __align__(16) ull s_u2w2[CC*8];
    __shared__ __align__(16) ull s_cb2n[CC*16];
    __shared__ __align__(16) ull s_csq2[16];
    __shared__ __align__(16) ull s_bu1[8];
    __shared__ __align__(16) ull s_bu2[8];
    __shared__ __align__(16) ull s_bt[8];
    __shared__ float red[4]; __shared__ unsigned redu[4];

    int tid = threadIdx.x;
    int tx = tid & 15, ty = tid >> 4;      // ty 0..7, rows 2ty, 2ty+1
    int gx0 = blockIdx.x * 16, gy0 = blockIdx.y * 16, b = blockIdx.z;
    const float* xb = x + b * HH * WW;

    for (int e = tid; e < CC*9*8; e += 128) {
        int q = e & 7; int t = (e >> 3) % 9; int ci = e / 72;
        s_w2[e] = pack2f(up1_w[(2*q*CC + ci)*9 + t], up1_w[((2*q+1)*CC + ci)*9 + t]);
    }
    for (int e = tid; e < CC*8; e += 128) {
        int q = e & 7; int ci = e >> 3;
        s_tw2[e]  = pack2f(tau_w[2*q*CC + ci],  tau_w[(2*q+1)*CC + ci]);
        s_u2w2[e] = pack2f(up2_w[2*q*CC + ci],  up2_w[(2*q+1)*CC + ci]);
    }
    for (int e = tid; e < CC*16; e += 128) {
        int j = e & 15; int c = e >> 4;
        s_cb2n[e] = pack2f(-2.f*cb[2*j*CC + c], -2.f*cb[(2*j+1)*CC + c]);
    }
    for (int e = tid; e < CC*9; e += 128) s_sw[e] = stem_w[e];
    if (tid < CC) s_sb[tid] = stem_b[tid];
    if (tid < 16) s_csq2[tid] = pack2f(g_csq[2*tid], g_csq[2*tid+1]);
    if (tid < 8) {
        s_bu1[tid] = pack2f(up1_b[2*tid], up1_b[2*tid+1]);
        s_bu2[tid] = pack2f(up2_b[2*tid], up2_b[2*tid+1]);
        s_bt[tid]  = pack2f(tau_b[2*tid], tau_b[2*tid+1]);
    }
    for (int p = tid; p < 400; p += 128) {
        int iy = p / 20, ix = p % 20;
        int gy = gy0 - 2 + iy, gx = gx0 - 2 + ix;
        xs[p] = (gy >= 0 && gy < HH && gx >= 0 && gx < WW) ? xb[gy*WW + gx] : 0.f;
    }
    __syncthreads();

    // ---- stem over 18x18 halo: per-thread pixel descriptors precomputed, weights in regs ----
    {
        int   xoff[3]; bool pval[3];
        #pragma unroll
        for (int i = 0; i < 3; i++) {
            int p = tid + i*128;
            if (p < 324) {
                int ly = p / 18, lx = p % 18;
                int gy = gy0 - 1 + ly, gx = gx0 - 1 + lx;
                pval[i] = (gy >= 0 && gy < HH && gx >= 0 && gx < WW);
                xoff[i] = ly*20 + lx;
            } else { pval[i] = false; xoff[i] = 0; }
        }
        for (int c = 0; c < CC; c++) {
            float w[9];
            #pragma unroll
            for (int t = 0; t < 9; t++) w[t] = s_sw[c*9 + t];
            float bb = s_sb[c];
            #pragma unroll
            for (int i = 0; i < 3; i++) {
                int p = tid + i*128;
                if (p < 324) {
                    float acc = 0.f;
                    if (pval[i]) {
                        acc = bb;
                        #pragma unroll
                        for (int t = 0; t < 9; t++)
                            acc = fmaf(w[t], xs[xoff[i] + (t/3)*20 + t%3], acc);
                        acc = fmaxf(acc, 0.f);
                    }
                    s0[c][p] = acc;
                }
            }
        }
    }
    __syncthreads();

    // ---- conv3x3 16->16, 2 px/thread ----
    ull y2a[8], y2b[8];
    #pragma unroll
    for (int q = 0; q < 8; q++) { y2a[q] = s_bu1[q]; y2b[q] = s_bu1[q]; }
    #pragma unroll 4
    for (int ci = 0; ci < CC; ci++) {
        const float* s0p = &s0[ci][0];
        #pragma unroll
        for (int tc = 0; tc < 3; tc++) {
            float v0 = s0p[(2*ty+0)*18 + tx + tc];
            float v1 = s0p[(2*ty+1)*18 + tx + tc];
            float v2 = s0p[(2*ty+2)*18 + tx + tc];
            float v3 = s0p[(2*ty+3)*18 + tx + tc];
            #pragma unroll
            for (int tr = 0; tr < 3; tr++) {
                int t = tr*3 + tc;
                float va = (tr == 0) ? v0 : ((tr == 1) ? v1 : v2);
                float vb = (tr == 0) ? v1 : ((tr == 1) ? v2 : v3);
                ull vva = pack2f(va, va), vvb = pack2f(vb, vb);
                const ulonglong2* wp = (const ulonglong2*)&s_w2[(ci*9 + t)*8];
                #pragma unroll
                for (int qq = 0; qq < 4; qq++) {
                    ulonglong2 w = wp[qq];
                    y2a[2*qq]   = fma2(vva, w.x, y2a[2*qq]);
                    y2a[2*qq+1] = fma2(vva, w.y, y2a[2*qq+1]);
                    y2b[2*qq]   = fma2(vvb, w.x, y2b[2*qq]);
                    y2b[2*qq+1] = fma2(vvb, w.y, y2b[2*qq+1]);
                }
            }
        }
    }

    // ---- delta = up2 @ relu(y) ----
    ull d2a[8], d2b[8];
    #pragma unroll
    for (int q = 0; q < 8; q++) { d2a[q] = s_bu2[q]; d2b[q] = s_bu2[q]; }
    #pragma unroll
    for (int q = 0; q < 8; q++) {
        float a0, a1, b0, b1;
        unpack2f(y2a[q], a0, a1); unpack2f(y2b[q], b0, b1);
        a0 = fmaxf(a0, 0.f); a1 = fmaxf(a1, 0.f);
        b0 = fmaxf(b0, 0.f); b1 = fmaxf(b1, 0.f);
        #pragma unroll
        for (int s = 0; s < 2; s++) {
            int ci = 2*q + s;
            float fa = s ? a1 : a0, fb = s ? b1 : b0;
            ull va = pack2f(fa, fa), vb = pack2f(fb, fb);
            const ulonglong2* wp = (const ulonglong2*)&s_u2w2[ci*8];
            #pragma unroll
            for (int qq = 0; qq < 4; qq++) {
                ulonglong2 w = wp[qq];
                d2a[2*qq]   = fma2(va, w.x, d2a[2*qq]);
                d2a[2*qq+1] = fma2(va, w.y, d2a[2*qq+1]);
                d2b[2*qq]   = fma2(vb, w.x, d2b[2*qq]);
                d2b[2*qq+1] = fma2(vb, w.y, d2b[2*qq+1]);
            }
        }
    }

    // ---- tau (center values read from smem) ----
    int ctra = (2*ty+1)*18 + (tx+1);
    int ctrb = (2*ty+2)*18 + (tx+1);
    ull t2a[8], t2b[8];
    #pragma unroll
    for (int q = 0; q < 8; q++) { t2a[q] = s_bt[q]; t2b[q] = s_bt[q]; }
    #pragma unroll 4
    for (int ci = 0; ci < CC; ci++) {
        float fa = s0[ci][ctra], fb = s0[ci][ctrb];
        ull va = pack2f(fa, fa), vb = pack2f(fb, fb);
        const ulonglong2* wp = (const ulonglong2*)&s_tw2[ci*8];
        #pragma unroll
        for (int qq = 0; qq < 4; qq++) {
            ulonglong2 w = wp[qq];
            t2a[2*qq]   = fma2(va, w.x, t2a[2*qq]);
            t2a[2*qq+1] = fma2(va, w.y, t2a[2*qq+1]);
            t2b[2*qq]   = fma2(vb, w.x, t2b[2*qq]);
            t2b[2*qq+1] = fma2(vb, w.y, t2b[2*qq+1]);
        }
    }

    // ---- blend + zsq ----
    float zA[CC], zB[CC]; float zsqa = 0.f, zsqb = 0.f;
    #pragma unroll
    for (int q = 0; q < 8; q++) {
        float tlo, thi, dlo, dhi;
        unpack2f(t2a[q], tlo, thi); unpack2f(d2a[q], dlo, dhi);
        {
            float blo = 1.f / (1.f + __expf(-tlo));
            float bhi = 1.f / (1.f + __expf(-thi));
            float zlo = fmaf(blo, s0[2*q][ctra],   (1.f - blo) * dlo);
            float zhi = fmaf(bhi, s0[2*q+1][ctra], (1.f - bhi) * dhi);
            zsqa = fmaf(zlo, zlo, zsqa); zsqa = fmaf(zhi, zhi, zsqa);
            zA[2*q] = zlo; zA[2*q+1] = zhi;
        }
        unpack2f(t2b[q], tlo, thi); unpack2f(d2b[q], dlo, dhi);
        {
            float blo = 1.f / (1.f + __expf(-tlo));
            float bhi = 1.f / (1.f + __expf(-thi));
            float zlo = fmaf(blo, s0[2*q][ctrb],   (1.f - blo) * dlo);
            float zhi = fmaf(bhi, s0[2*q+1][ctrb], (1.f - bhi) * dhi);
            zsqb = fmaf(zlo, zlo, zsqb); zsqb = fmaf(zhi, zhi, zsqb);
            zB[2*q] = zlo; zB[2*q+1] = zhi;
        }
    }

    int bka, bkb; float la, lb;
    vq2_seq(zA, zB, zsqa, zsqb, s_cb2n, s_csq2, bka, bkb, la, lb);

    int gya = gy0 + 2*ty;
    g_idxA[(b*HH + gya    )*WW + gx0 + tx] = (unsigned char)bka;
    g_idxA[(b*HH + gya + 1)*WW + gx0 + tx] = (unsigned char)bkb;
    block_accumulate(la + lb, (1u << bka) | (1u << bkb), 0, red, redu);
}

// ---------------- steps 2..5 common body (round-4 layout), templated on LAST ----------------
template<int LAST>
__device__ __forceinline__ void step_body(const float* up1_b, const float* up2_w,
                                          const float* up2_b, const float* cb,
                                          float* out, int slot) {
    __shared__ __align__(16) ull s_M2[9*8*33];    // [t][q][k], sentinel k=32 -> 0
    __shared__ __align__(16) ull s_P2[8*32];
    __shared__ __align__(16) ull s_Q2[8*32];
    __shared__ __align__(16) ull s_cb2n[CC*16];
    __shared__ __align__(16) ull s_csq2[16];
    __shared__ __align__(16) ull s_bu1[8];
    __shared__ __align__(16) ull s_bu2[8];
    __shared__ __align__(16) ull s_u2w2[CC*8];
    __shared__ unsigned char s_idx[34*18];
    __shared__ float s_sigD[KK];
    __shared__ float red[8]; __shared__ unsigned redu[8];

    int tid = threadIdx.x;
    for (int e = tid; e < 9*8*33; e += 256) {
        int k = e % 33; int q = (e/33) & 7; int t = e/(33*8);
        float lo = 0.f, hi = 0.f;
        if (k < 32) { lo = g_M[(t*CC + 2*q)*KK + k]; hi = g_M[(t*CC + 2*q+1)*KK + k]; }
        s_M2[e] = pack2f(lo, hi);
    }
    for (int e = tid; e < 8*32; e += 256) {
        int k = e & 31; int q = e >> 5;
        s_P2[e] = pack2f(g_P[2*q*KK + k], g_P[(2*q+1)*KK + k]);
        s_Q2[e] = pack2f(g_Q[2*q*KK + k], g_Q[(2*q+1)*KK + k]);
    }
    for (int e = tid; e < CC*16; e += 256) {
        int j = e & 15; int c = e >> 4;
        s_cb2n[e] = pack2f(-2.f*cb[2*j*CC + c], -2.f*cb[(2*j+1)*CC + c]);
    }
    if (tid < 16) s_csq2[tid] = pack2f(g_csq[2*tid], g_csq[2*tid+1]);
    if (tid < 8) {
        s_bu1[tid] = pack2f(up1_b[2*tid], up1_b[2*tid+1]);
        s_bu2[tid] = pack2f(up2_b[2*tid], up2_b[2*tid+1]);
    }
    for (int e = tid; e < CC*8; e += 256) {
        int q = e & 7; int ci = e >> 3;
        s_u2w2[e] = pack2f(up2_w[2*q*CC + ci], up2_w[(2*q+1)*CC + ci]);
    }
    if (LAST) { if (tid < KK) s_sigD[tid] = g_sigD[tid]; }

    const unsigned char* ibuf = (slot & 1) ? g_idxA : g_idxB;
    unsigned char* obuf       = (slot & 1) ? g_idxB : g_idxA;

    int tx = tid & 15, ty = tid >> 4;
    float loc_loss = 0.f; unsigned loc_mask = 0u;

    for (int tile = blockIdx.x; tile < NT2; tile += gridDim.x) {
        int b = tile >> 7; int rem = tile & 127;
        int gy0 = (rem >> 4) << 5, gx0 = (rem & 15) << 4;
        const unsigned char* ib = ibuf + b * HH * WW;

        __syncthreads();
        for (int p = tid; p < 34*18; p += 256) {
            int iy = p / 18, ix = p % 18;
            int gy = gy0 - 1 + iy, gx = gx0 - 1 + ix;
            s_idx[p] = (gy >= 0 && gy < HH && gx >= 0 && gx < WW) ? ib[gy*WW + gx] : 32;
        }
        __syncthreads();

        // conv via table adds; idx rows shared between the 2 pixels
        ull y2a[8], y2b[8];
        #pragma unroll
        for (int q = 0; q < 8; q++) { y2a[q] = s_bu1[q]; y2b[q] = s_bu1[q]; }
        #pragma unroll
        for (int tc = 0; tc < 3; tc++) {
            int i0 = s_idx[(2*ty+0)*18 + tx + tc];
            int i1 = s_idx[(2*ty+1)*18 + tx + tc];
            int i2 = s_idx[(2*ty+2)*18 + tx + tc];
            int i3 = s_idx[(2*ty+3)*18 + tx + tc];
            #pragma unroll
            for (int tr = 0; tr < 3; tr++) {
                int t = tr*3 + tc;
                int ka = (tr == 0) ? i0 : ((tr == 1) ? i1 : i2);
                int kb = (tr == 0) ? i1 : ((tr == 1) ? i2 : i3);
                const ull* Ma = &s_M2[t*8*33 + ka];
                const ull* Mb = &s_M2[t*8*33 + kb];
                #pragma unroll
                for (int q = 0; q < 8; q++) {
                    y2a[q] = add2(y2a[q], Ma[q*33]);
                    y2b[q] = add2(y2b[q], Mb[q*33]);
                }
            }
        }

        // delta, relu+unpack on the fly
        ull d2a[8], d2b[8];
        #pragma unroll
        for (int q = 0; q < 8; q++) { d2a[q] = s_bu2[q]; d2b[q] = s_bu2[q]; }
        #pragma unroll
        for (int q = 0; q < 8; q++) {
            float a0, a1, b0, b1;
            unpack2f(y2a[q], a0, a1); unpack2f(y2b[q], b0, b1);
            a0 = fmaxf(a0, 0.f); a1 = fmaxf(a1, 0.f);
            b0 = fmaxf(b0, 0.f); b1 = fmaxf(b1, 0.f);
            #pragma unroll
            for (int s = 0; s < 2; s++) {
                int ci = 2*q + s;
                float fa = s ? a1 : a0, fb = s ? b1 : b0;
                ull va = pack2f(fa, fa), vb = pack2f(fb, fb);
                const ulonglong2* wp = (const ulonglong2*)&s_u2w2[ci*8];
                #pragma unroll
                for (int qq = 0; qq < 4; qq++) {
                    ulonglong2 w = wp[qq];
                    d2a[2*qq]   = fma2(va, w.x, d2a[2*qq]);
                    d2a[2*qq+1] = fma2(va, w.y, d2a[2*qq+1]);
                    d2b[2*qq]   = fma2(vb, w.x, d2b[2*qq]);
                    d2b[2*qq+1] = fma2(vb, w.y, d2b[2*qq+1]);
                }
            }
        }

        // blend via P/Q tables on center codes
        int kca = s_idx[(2*ty+1)*18 + tx + 1];
        int kcb = s_idx[(2*ty+2)*18 + tx + 1];
        float zA[CC], zB[CC]; float zsqa = 0.f, zsqb = 0.f;
        #pragma unroll
        for (int q = 0; q < 8; q++) {
            ull za = fma2(s_Q2[q*32 + kca], d2a[q], s_P2[q*32 + kca]);
            ull zb = fma2(s_Q2[q*32 + kcb], d2b[q], s_P2[q*32 + kcb]);
            float lo, hi;
            unpack2f(za, lo, hi); zsqa = fmaf(lo, lo, zsqa); zsqa = fmaf(hi, hi, zsqa);
            zA[2*q] = lo; zA[2*q+1] = hi;
            unpack2f(zb, lo, hi); zsqb = fmaf(lo, lo, zsqb); zsqb = fmaf(hi, hi, zsqb);
            zB[2*q] = lo; zB[2*q+1] = hi;
        }

        int bka, bkb; float la, lb;
        vq2_seq(zA, zB, zsqa, zsqb, s_cb2n, s_csq2, bka, bkb, la, lb);

        int gya = gy0 + 2*ty;
        if (LAST) {
            out[(b*HH + gya    )*WW + gx0 + tx] = s_sigD[bka];
            out[(b*HH + gya + 1)*WW + gx0 + tx] = s_sigD[bkb];
        } else {
            obuf[(b*HH + gya    )*WW + gx0 + tx] = (unsigned char)bka;
            obuf[(b*HH + gya + 1)*WW + gx0 + tx] = (unsigned char)bkb;
        }
        loc_loss += la + lb;
        loc_mask |= (1u << bka) | (1u << bkb);
    }
    __syncthreads();
    block_accumulate(loc_loss, loc_mask, slot, red, redu);
}

__global__ __launch_bounds__(256, 3)
void k_step_mid(const float* __restrict__ up1_b, const float* __restrict__ up2_w,
                const float* __restrict__ up2_b, const float* __restrict__ cb, int slot) {
    step_body<0>(up1_b, up2_w, up2_b, cb, nullptr, slot);
}

__global__ __launch_bounds__(256, 3)
void k_step_last(const float* __restrict__ up1_b, const float* __restrict__ up2_w,
                 const float* __restrict__ up2_b, const float* __restrict__ cb,
                 float* __restrict__ out) {
    step_body<1>(up1_b, up2_w, up2_b, cb, out, 4);
}

// ---------------- scalars ----------------
__global__ void k_final(float* __restrict__ out) {
    float vq = 0.f, us = 0.f;
    #pragma unroll
    for (int s = 0; s < NSTEPS; s++) {
        vq += 1.25f * g_sse[s] / (float)NELEM;
        us += (float)__popc(g_used[s]) / (float)KK;
    }
    out[NPIX]     = vq / (float)NSTEPS;
    out[NPIX + 1] = us / (float)NSTEPS;
}

extern "C" void kernel_launch(void* const* d_in, const int* in_sizes, int n_in,
                              void* d_out, int out_size) {
    const float* x      = (const float*)d_in[0];
    const float* stem_w = (const float*)d_in[1];
    const float* stem_b = (const float*)d_in[2];
    const float* up1_w  = (const float*)d_in[3];
    const float* up1_b  = (const float*)d_in[4];
    const float* up2_w  = (const float*)d_in[5];
    const float* up2_b  = (const float*)d_in[6];
    const float* tau_w  = (const float*)d_in[7];
    const float* tau_b  = (const float*)d_in[8];
    const float* cb     = (const float*)d_in[9];
    const float* dec_w  = (const float*)d_in[10];
    const float* dec_b  = (const float*)d_in[11];
    float* out = (float*)d_out;

    k_tables<<<1, 512>>>(up1_w, tau_w, tau_b, cb, dec_w, dec_b);

    dim3 grid1(WW/16, HH/16, BATCH);
    k_step1<<<grid1, 128>>>(x, stem_w, stem_b, up1_w, up1_b, up2_w, up2_b, tau_w, tau_b, cb);
    for (int s = 1; s < 4; s++)
        k_step_mid<<<1332, 256>>>(up1_b, up2_w, up2_b, cb, s);
    k_step_last<<<1332, 256>>>(up1_b, up2_w, up2_b, cb, out);

    k_final<<<1, 1>>>(out);
}